// round 6
// baseline (speedup 1.0000x reference)
#include <cuda_runtime.h>
#include <math.h>

#define NA     4096
#define NWORDS 16384
#define DIM    128
#define NZCAP  256
#define CK     23

// ------------------------- scratch (no allocations allowed) -------------------------
__device__ float g_xs[NA * DIM];
__device__ float g_hs[NA * DIM];
__device__ int   g_nzidx[NA * NZCAP];
__device__ int   g_nzcnt[NA];
__device__ float g_imgA[NWORDS * DIM];
__device__ float g_imgB[NWORDS * DIM];
__device__ float g_hsatt[NWORDS * DIM];
__device__ float g_part[128 * DIM];
__device__ float g_compound[DIM];
__device__ float g_hatt[DIM];
__device__ float g_protein[DIM];

// ------------------------- f32x2 helpers -------------------------
typedef unsigned long long u64;
__device__ __forceinline__ void ffma2(u64& d, u64 a, u64 b) {
    asm("fma.rn.f32x2 %0, %1, %2, %0;" : "+l"(d) : "l"(a), "l"(b));
}
__device__ __forceinline__ float lo32(u64 v) {
    return __uint_as_float((unsigned)(v & 0xffffffffull));
}
__device__ __forceinline__ float hi32(u64 v) {
    return __uint_as_float((unsigned)(v >> 32));
}

// ------------------------- embedding gather -------------------------
__global__ void gather_kernel(const int* __restrict__ idx, const float* __restrict__ emb,
                              float* __restrict__ out, int n) {
    int i = blockIdx.x * blockDim.x + threadIdx.x;
    if (i < n * DIM) {
        int row = i >> 7;
        int c   = i & 127;
        out[i] = emb[(size_t)idx[row] * DIM + c];
    }
}

// ------------------------- sparse adjacency build (deterministic, ordered) -------------------------
__global__ void build_nz(const float* __restrict__ adj) {
    int warp = (blockIdx.x * blockDim.x + threadIdx.x) >> 5;
    int lane = threadIdx.x & 31;
    if (warp >= NA) return;
    const float* row = adj + (size_t)warp * NA;
    int base = 0;
    for (int j0 = 0; j0 < NA; j0 += 32) {
        float v = row[j0 + lane];
        unsigned mask = __ballot_sync(0xffffffffu, v != 0.f);
        if (v != 0.f) {
            int r = __popc(mask & ((1u << lane) - 1));
            int p = base + r;
            if (p < NZCAP) g_nzidx[warp * NZCAP + p] = j0 + lane;
        }
        base += __popc(mask);
    }
    if (lane == 0) g_nzcnt[warp] = base < NZCAP ? base : NZCAP;
}

// ------------------------- Y = relu(X @ W^T + b), N=K=128 -------------------------
__global__ void __launch_bounds__(256) linear_relu(const float* __restrict__ X,
                                                   const float* __restrict__ W,
                                                   const float* __restrict__ b,
                                                   float* __restrict__ Y) {
    extern __shared__ float sm[];
    float* sW = sm;                 // [128][129]
    float* sX = sm + 128 * 129;     // [32][128]
    int tid = threadIdx.x;
    for (int idx = tid; idx < 128 * 128; idx += 256) {
        int j = idx >> 7, k = idx & 127;
        sW[j * 129 + k] = W[idx];
    }
    int r0 = blockIdx.x * 32;
    for (int idx = tid; idx < 32 * 128; idx += 256)
        sX[idx] = X[(size_t)r0 * 128 + idx];
    __syncthreads();

    int lane = tid & 31;
    int rg   = tid >> 5;
    int i0   = rg * 4;
    float acc[4][4];
#pragma unroll
    for (int r = 0; r < 4; ++r)
#pragma unroll
        for (int q = 0; q < 4; ++q) acc[r][q] = 0.f;

#pragma unroll 4
    for (int k = 0; k < 128; ++k) {
        float a0 = sX[(i0 + 0) * 128 + k];
        float a1 = sX[(i0 + 1) * 128 + k];
        float a2 = sX[(i0 + 2) * 128 + k];
        float a3 = sX[(i0 + 3) * 128 + k];
#pragma unroll
        for (int q = 0; q < 4; ++q) {
            float w = sW[(lane + q * 32) * 129 + k];
            acc[0][q] += a0 * w;
            acc[1][q] += a1 * w;
            acc[2][q] += a2 * w;
            acc[3][q] += a3 * w;
        }
    }
#pragma unroll
    for (int r = 0; r < 4; ++r) {
        int row = r0 + i0 + r;
#pragma unroll
        for (int q = 0; q < 4; ++q) {
            int j = lane + q * 32;
            float v = acc[r][q] + b[j];
            Y[(size_t)row * 128 + j] = v > 0.f ? v : 0.f;
        }
    }
}

// ------------------------- xs += A_sparse @ hs (warp-per-row, float4 lanes) -------------------------
__global__ void __launch_bounds__(256) spmm_add(const float* __restrict__ hs) {
    int row  = blockIdx.x * 8 + (threadIdx.x >> 5);
    int lane = threadIdx.x & 31;
    int cnt = g_nzcnt[row];
    const int* nz = g_nzidx + row * NZCAP;

    float4 a0 = make_float4(0.f, 0.f, 0.f, 0.f);
    float4 a1 = make_float4(0.f, 0.f, 0.f, 0.f);
    int t = 0;
    for (; t + 2 <= cnt; t += 2) {
        int j0 = nz[t], j1 = nz[t + 1];
        float4 v0 = *reinterpret_cast<const float4*>(hs + (size_t)j0 * DIM + lane * 4);
        float4 v1 = *reinterpret_cast<const float4*>(hs + (size_t)j1 * DIM + lane * 4);
        a0.x += v0.x; a0.y += v0.y; a0.z += v0.z; a0.w += v0.w;
        a1.x += v1.x; a1.y += v1.y; a1.z += v1.z; a1.w += v1.w;
    }
    if (t < cnt) {
        float4 v0 = *reinterpret_cast<const float4*>(hs + (size_t)nz[t] * DIM + lane * 4);
        a0.x += v0.x; a0.y += v0.y; a0.z += v0.z; a0.w += v0.w;
    }
    float4* dst = reinterpret_cast<float4*>(g_xs + (size_t)row * DIM + lane * 4);
    float4 x = *dst;
    x.x += a0.x + a1.x;
    x.y += a0.y + a1.y;
    x.z += a0.z + a1.z;
    x.w += a0.w + a1.w;
    *dst = x;
}

// ------------------------- deterministic column-sum reductions -------------------------
__global__ void colsum_partial(const float* __restrict__ X, float* __restrict__ part,
                               int rows_per_block) {
    int c = threadIdx.x;
    int r0 = blockIdx.x * rows_per_block;
    float acc = 0.f;
    for (int r = 0; r < rows_per_block; ++r) acc += X[(size_t)(r0 + r) * DIM + c];
    part[blockIdx.x * DIM + c] = acc;
}

__global__ void colsum_combine(const float* __restrict__ part, int nparts, float scale,
                               float* __restrict__ out) {
    int c = threadIdx.x;
    float acc = 0.f;
    for (int b = 0; b < nparts; ++b) acc += part[b * DIM + c];
    out[c] = acc * scale;
}

// ------------------------- 23x23 SAME conv + bias + leaky_relu -------------------------
// Each thread: 2 adjacent column-pairs (out cols 2tx, 2tx+1, 2tx+64, 2tx+65) x 8 rows.
// Inputs loaded ONCE per d and shared between the two pairs (weight cols d and d-1).
// Parity-split smem layout keeps LDS.64 conflict-free (thread stride = 8B).
// Weight table zero-padded (25 cols) -> branchless edge handling.
#define SPITCH 88   // 2 * 44 (43 pairs per parity + 1 pad)
__global__ void __launch_bounds__(128, 4) conv_leaky(const float* __restrict__ in,
                                                     float* __restrict__ out,
                                                     const float* __restrict__ kw,
                                                     const float* __restrict__ kb) {
    __shared__ float2 s_in2[54 * SPITCH];
    __shared__ float2 s_kp[CK * 25];   // [dr][cc]: cc==0 or 24 -> 0, else w[dr][cc-1] dup'd
    int tx  = threadIdx.x;             // 0..31
    int tid = tx + threadIdx.y * 32;   // 128 threads
    int r0  = blockIdx.x * 32;

    // input tile: rows r0-11 .. r0+42; pair qi (0..85) covers cols (qi-11, qi+53)
    // placement: row*SPITCH + (qi&1)*44 + (qi>>1)
    for (int idx = tid; idx < 54 * 86; idx += 128) {
        int rr = idx / 86;
        int qi = idx - rr * 86;
        int gr = r0 - 11 + rr;
        int q  = qi - 11;
        float lo = 0.f, hi = 0.f;
        if (gr >= 0 && gr < NWORDS) {
            const float* grow = in + (size_t)gr * DIM;
            if (q >= 0)       lo = grow[q];
            if (q + 64 < 128) hi = grow[q + 64];
        }
        s_in2[rr * SPITCH + (qi & 1) * 44 + (qi >> 1)] = make_float2(lo, hi);
    }
    for (int idx = tid; idx < CK * 25; idx += 128) {
        int dr = idx / 25, cc = idx - dr * 25;
        float w = (cc >= 1 && cc <= 23) ? kw[dr * CK + (cc - 1)] : 0.f;
        s_kp[idx] = make_float2(w, w);
    }
    __syncthreads();

    float bias = kb[0];
    int rbase  = threadIdx.y * 8;

    u64 acc0[8], acc1[8];
#pragma unroll
    for (int o = 0; o < 8; ++o) { acc0[o] = 0ull; acc1[o] = 0ull; }

    const u64* sin = reinterpret_cast<const u64*>(s_in2);
    const u64* skp = reinterpret_cast<const u64*>(s_kp);

#pragma unroll 1
    for (int d = 0; d < 24; ++d) {
        const u64* col = sin + rbase * SPITCH + (d & 1) * 44 + (d >> 1) + tx;

        // batch 1: dr 0..11, rows R 0..18
        {
            u64 w0[12], w1[12];
#pragma unroll
            for (int dr = 0; dr < 12; ++dr) {
                w0[dr] = skp[dr * 25 + d + 1];  // pair0: weight col d   (0 when d==23)
                w1[dr] = skp[dr * 25 + d];      // pair1: weight col d-1 (0 when d==0)
            }
#pragma unroll
            for (int R = 0; R < 19; ++R) {
                u64 v2 = col[R * SPITCH];
#pragma unroll
                for (int dr = 0; dr < 12; ++dr) {
                    int o = R - dr;
                    if (o >= 0 && o < 8) {
                        ffma2(acc0[o], v2, w0[dr]);
                        ffma2(acc1[o], v2, w1[dr]);
                    }
                }
            }
        }
        // batch 2: dr 12..22, rows R 12..29
        {
            u64 w0[11], w1[11];
#pragma unroll
            for (int dr = 0; dr < 11; ++dr) {
                w0[dr] = skp[(dr + 12) * 25 + d + 1];
                w1[dr] = skp[(dr + 12) * 25 + d];
            }
#pragma unroll
            for (int R = 12; R < 30; ++R) {
                u64 v2 = col[R * SPITCH];
#pragma unroll
                for (int dr = 0; dr < 11; ++dr) {
                    int o = R - (dr + 12);
                    if (o >= 0 && o < 8) {
                        ffma2(acc0[o], v2, w0[dr]);
                        ffma2(acc1[o], v2, w1[dr]);
                    }
                }
            }
        }
    }

#pragma unroll
    for (int o = 0; o < 8; ++o) {
        int row = r0 + rbase + o;
        float vA = lo32(acc0[o]) + bias;  vA = vA > 0.f ? vA : 0.01f * vA;
        float vB = lo32(acc1[o]) + bias;  vB = vB > 0.f ? vB : 0.01f * vB;
        float vC = hi32(acc0[o]) + bias;  vC = vC > 0.f ? vC : 0.01f * vC;
        float vD = hi32(acc1[o]) + bias;  vD = vD > 0.f ? vD : 0.01f * vD;
        *reinterpret_cast<float2*>(out + (size_t)row * DIM + 2 * tx)      = make_float2(vA, vB);
        *reinterpret_cast<float2*>(out + (size_t)row * DIM + 2 * tx + 64) = make_float2(vC, vD);
    }
}

// ------------------------- h = relu(compound @ W_att^T + b) (single row) -------------------------
__global__ void small_linear_relu(const float* __restrict__ xin, const float* __restrict__ W,
                                  const float* __restrict__ b, float* __restrict__ out) {
    __shared__ float sx[DIM];
    int j = threadIdx.x;
    sx[j] = xin[j];
    __syncthreads();
    float acc = b[j];
    for (int k = 0; k < DIM; ++k) acc += sx[k] * W[j * DIM + k];
    out[j] = acc > 0.f ? acc : 0.f;
}

// ------------------------- protein = mean_m tanh(h . hs_m) * hs_m  (partials) -------------------------
__global__ void protein_partial(const float* __restrict__ hs) {
    __shared__ float sh[DIM];
    __shared__ float sacc[4][DIM];
    int tid  = threadIdx.x;
    int lane = tid & 31;
    int w    = tid >> 5;
    sh[tid] = g_hatt[tid];
    __syncthreads();
    float h0 = sh[lane], h1 = sh[lane + 32], h2 = sh[lane + 64], h3 = sh[lane + 96];
    float a0 = 0.f, a1 = 0.f, a2 = 0.f, a3 = 0.f;
    int m0 = blockIdx.x * 128 + w * 32;
    for (int mi = 0; mi < 32; ++mi) {
        const float* row = hs + (size_t)(m0 + mi) * DIM;
        float d = row[lane] * h0 + row[lane + 32] * h1 + row[lane + 64] * h2 + row[lane + 96] * h3;
#pragma unroll
        for (int off = 16; off; off >>= 1) d += __shfl_xor_sync(0xffffffffu, d, off);
        float t = tanhf(d);
        float4 v = *reinterpret_cast<const float4*>(row + lane * 4);
        a0 += t * v.x;
        a1 += t * v.y;
        a2 += t * v.z;
        a3 += t * v.w;
    }
    sacc[w][lane * 4 + 0] = a0;
    sacc[w][lane * 4 + 1] = a1;
    sacc[w][lane * 4 + 2] = a2;
    sacc[w][lane * 4 + 3] = a3;
    __syncthreads();
    g_part[blockIdx.x * DIM + tid] =
        sacc[0][tid] + sacc[1][tid] + sacc[2][tid] + sacc[3][tid];
}

// ------------------------- final 2-layer MLP + scalar head -------------------------
__global__ void final_mlp(const float* __restrict__ Wout, const float* __restrict__ bout,
                          const float* __restrict__ Wint, const float* __restrict__ bint,
                          float* __restrict__ out) {
    __shared__ float cat[256];
    __shared__ float red[256];
    int t = threadIdx.x;
    if (t < 128) {
        cat[t]       = g_compound[t];
        cat[t + 128] = g_protein[t];
    }
    __syncthreads();
    for (int l = 0; l < 2; ++l) {
        const float* Wl = Wout + l * 256 * 256;
        float acc = bout[l * 256 + t];
        for (int k = 0; k < 256; ++k) acc += cat[k] * Wl[t * 256 + k];
        __syncthreads();
        cat[t] = acc > 0.f ? acc : 0.f;
        __syncthreads();
    }
    red[t] = cat[t] * Wint[t];
    __syncthreads();
    for (int s = 128; s; s >>= 1) {
        if (t < s) red[t] += red[t + s];
        __syncthreads();
    }
    if (t == 0) out[0] = red[0] + bint[0];
}

// ------------------------- launch -------------------------
extern "C" void kernel_launch(void* const* d_in, const int* in_sizes, int n_in,
                              void* d_out, int out_size) {
    const int*   fingerprints = (const int*)d_in[0];
    const float* adjacency    = (const float*)d_in[1];
    const int*   words        = (const int*)d_in[2];
    const float* emb_fp       = (const float*)d_in[3];
    const float* emb_word     = (const float*)d_in[4];
    const float* W_gnn_w      = (const float*)d_in[5];
    const float* W_gnn_b      = (const float*)d_in[6];
    const float* conv_w       = (const float*)d_in[7];
    const float* conv_b       = (const float*)d_in[8];
    const float* W_att_w      = (const float*)d_in[9];
    const float* W_att_b      = (const float*)d_in[10];
    const float* W_out_w      = (const float*)d_in[11];
    const float* W_out_b      = (const float*)d_in[12];
    const float* W_int_w      = (const float*)d_in[13];
    const float* W_int_b      = (const float*)d_in[14];
    float* out = (float*)d_out;

    float *xs, *hs, *imgA, *imgB, *hsatt, *part, *comp, *hatt, *prot;
    cudaGetSymbolAddress((void**)&xs,    g_xs);
    cudaGetSymbolAddress((void**)&hs,    g_hs);
    cudaGetSymbolAddress((void**)&imgA,  g_imgA);
    cudaGetSymbolAddress((void**)&imgB,  g_imgB);
    cudaGetSymbolAddress((void**)&hsatt, g_hsatt);
    cudaGetSymbolAddress((void**)&part,  g_part);
    cudaGetSymbolAddress((void**)&comp,  g_compound);
    cudaGetSymbolAddress((void**)&hatt,  g_hatt);
    cudaGetSymbolAddress((void**)&prot,  g_protein);

    int smem_lin = (128 * 129 + 32 * 128) * (int)sizeof(float);
    cudaFuncSetAttribute(linear_relu, cudaFuncAttributeMaxDynamicSharedMemorySize, smem_lin);

    // ---- protein branch first (ncu -s 5 -c 1 lands on conv3 = launch #6) ----
    gather_kernel<<<(NA * DIM + 255) / 256, 256>>>(fingerprints, emb_fp, xs, NA);       // 1
    build_nz<<<NA / 8, 256>>>(adjacency);                                               // 2
    gather_kernel<<<(NWORDS * DIM + 255) / 256, 256>>>(words, emb_word, imgA, NWORDS);  // 3
    conv_leaky<<<NWORDS / 32, dim3(32, 4)>>>(imgA, imgB, conv_w + 0 * CK * CK, conv_b + 0); // 4
    conv_leaky<<<NWORDS / 32, dim3(32, 4)>>>(imgB, imgA, conv_w + 1 * CK * CK, conv_b + 1); // 5
    conv_leaky<<<NWORDS / 32, dim3(32, 4)>>>(imgA, imgB, conv_w + 2 * CK * CK, conv_b + 2); // 6

    // ---- compound (GNN) ----
    for (int l = 0; l < 3; ++l) {
        linear_relu<<<NA / 32, 256, smem_lin>>>(xs, W_gnn_w + l * DIM * DIM,
                                                W_gnn_b + l * DIM, hs);
        spmm_add<<<NA / 8, 256>>>(hs);
    }
    colsum_partial<<<32, 128>>>(xs, part, NA / 32);
    colsum_combine<<<1, 128>>>(part, 32, 1.0f / NA, comp);

    // ---- protein attention ----
    linear_relu<<<NWORDS / 32, 256, smem_lin>>>(imgB, W_att_w, W_att_b, hsatt);
    small_linear_relu<<<1, 128>>>(comp, W_att_w, W_att_b, hatt);
    protein_partial<<<NWORDS / 128, 128>>>(hsatt);
    colsum_combine<<<1, 128>>>(part, 128, 1.0f / NWORDS, prot);

    // ---- head ----
    final_mlp<<<1, 256>>>(W_out_w, W_out_b, W_int_w, W_int_b, out);
}

// round 7
// speedup vs baseline: 1.0992x; 1.0992x over previous
#include <cuda_runtime.h>
#include <math.h>

#define NA     4096
#define NWORDS 16384
#define DIM    128
#define NZCAP  256
#define CK     23

// ------------------------- scratch (no allocations allowed) -------------------------
__device__ float g_xs[NA * DIM];
__device__ float g_hs[NA * DIM];
__device__ int   g_nzidx[NA * NZCAP];
__device__ int   g_nzcnt[NA];
__device__ float g_imgA[NWORDS * DIM];
__device__ float g_imgB[NWORDS * DIM];
__device__ float g_hsatt[NWORDS * DIM];
__device__ float g_part[128 * DIM];
__device__ float g_compound[DIM];
__device__ float g_hatt[DIM];
__device__ float g_protein[DIM];

// ------------------------- f32x2 helpers -------------------------
typedef unsigned long long u64;
__device__ __forceinline__ void ffma2(u64& d, u64 a, u64 b) {
    asm("fma.rn.f32x2 %0, %1, %2, %0;" : "+l"(d) : "l"(a), "l"(b));
}
__device__ __forceinline__ float lo32(u64 v) {
    return __uint_as_float((unsigned)(v & 0xffffffffull));
}
__device__ __forceinline__ float hi32(u64 v) {
    return __uint_as_float((unsigned)(v >> 32));
}

// ------------------------- embedding gather -------------------------
__global__ void gather_kernel(const int* __restrict__ idx, const float* __restrict__ emb,
                              float* __restrict__ out, int n) {
    int i = blockIdx.x * blockDim.x + threadIdx.x;
    if (i < n * DIM) {
        int row = i >> 7;
        int c   = i & 127;
        out[i] = emb[(size_t)idx[row] * DIM + c];
    }
}

// ------------------------- sparse adjacency build (deterministic, ordered) -------------------------
__global__ void build_nz(const float* __restrict__ adj) {
    int warp = (blockIdx.x * blockDim.x + threadIdx.x) >> 5;
    int lane = threadIdx.x & 31;
    if (warp >= NA) return;
    const float* row = adj + (size_t)warp * NA;
    int base = 0;
    for (int j0 = 0; j0 < NA; j0 += 32) {
        float v = row[j0 + lane];
        unsigned mask = __ballot_sync(0xffffffffu, v != 0.f);
        if (v != 0.f) {
            int r = __popc(mask & ((1u << lane) - 1));
            int p = base + r;
            if (p < NZCAP) g_nzidx[warp * NZCAP + p] = j0 + lane;
        }
        base += __popc(mask);
    }
    if (lane == 0) g_nzcnt[warp] = base < NZCAP ? base : NZCAP;
}

// ------------------------- Y = relu(X @ W^T + b), N=K=128 -------------------------
__global__ void __launch_bounds__(256) linear_relu(const float* __restrict__ X,
                                                   const float* __restrict__ W,
                                                   const float* __restrict__ b,
                                                   float* __restrict__ Y) {
    extern __shared__ float sm[];
    float* sW = sm;                 // [128][129]
    float* sX = sm + 128 * 129;     // [32][128]
    int tid = threadIdx.x;
    for (int idx = tid; idx < 128 * 128; idx += 256) {
        int j = idx >> 7, k = idx & 127;
        sW[j * 129 + k] = W[idx];
    }
    int r0 = blockIdx.x * 32;
    for (int idx = tid; idx < 32 * 128; idx += 256)
        sX[idx] = X[(size_t)r0 * 128 + idx];
    __syncthreads();

    int lane = tid & 31;
    int rg   = tid >> 5;
    int i0   = rg * 4;
    float acc[4][4];
#pragma unroll
    for (int r = 0; r < 4; ++r)
#pragma unroll
        for (int q = 0; q < 4; ++q) acc[r][q] = 0.f;

#pragma unroll 4
    for (int k = 0; k < 128; ++k) {
        float a0 = sX[(i0 + 0) * 128 + k];
        float a1 = sX[(i0 + 1) * 128 + k];
        float a2 = sX[(i0 + 2) * 128 + k];
        float a3 = sX[(i0 + 3) * 128 + k];
#pragma unroll
        for (int q = 0; q < 4; ++q) {
            float w = sW[(lane + q * 32) * 129 + k];
            acc[0][q] += a0 * w;
            acc[1][q] += a1 * w;
            acc[2][q] += a2 * w;
            acc[3][q] += a3 * w;
        }
    }
#pragma unroll
    for (int r = 0; r < 4; ++r) {
        int row = r0 + i0 + r;
#pragma unroll
        for (int q = 0; q < 4; ++q) {
            int j = lane + q * 32;
            float v = acc[r][q] + b[j];
            Y[(size_t)row * 128 + j] = v > 0.f ? v : 0.f;
        }
    }
}

// ------------------------- xs += A_sparse @ hs (warp-per-row, float4 lanes) -------------------------
__global__ void __launch_bounds__(256) spmm_add(const float* __restrict__ hs) {
    int row  = blockIdx.x * 8 + (threadIdx.x >> 5);
    int lane = threadIdx.x & 31;
    int cnt = g_nzcnt[row];
    const int* nz = g_nzidx + row * NZCAP;

    float4 a0 = make_float4(0.f, 0.f, 0.f, 0.f);
    float4 a1 = make_float4(0.f, 0.f, 0.f, 0.f);
    int t = 0;
    for (; t + 2 <= cnt; t += 2) {
        int j0 = nz[t], j1 = nz[t + 1];
        float4 v0 = *reinterpret_cast<const float4*>(hs + (size_t)j0 * DIM + lane * 4);
        float4 v1 = *reinterpret_cast<const float4*>(hs + (size_t)j1 * DIM + lane * 4);
        a0.x += v0.x; a0.y += v0.y; a0.z += v0.z; a0.w += v0.w;
        a1.x += v1.x; a1.y += v1.y; a1.z += v1.z; a1.w += v1.w;
    }
    if (t < cnt) {
        float4 v0 = *reinterpret_cast<const float4*>(hs + (size_t)nz[t] * DIM + lane * 4);
        a0.x += v0.x; a0.y += v0.y; a0.z += v0.z; a0.w += v0.w;
    }
    float4* dst = reinterpret_cast<float4*>(g_xs + (size_t)row * DIM + lane * 4);
    float4 x = *dst;
    x.x += a0.x + a1.x;
    x.y += a0.y + a1.y;
    x.z += a0.z + a1.z;
    x.w += a0.w + a1.w;
    *dst = x;
}

// ------------------------- deterministic column-sum reductions -------------------------
__global__ void colsum_partial(const float* __restrict__ X, float* __restrict__ part,
                               int rows_per_block) {
    int c = threadIdx.x;
    int r0 = blockIdx.x * rows_per_block;
    float acc = 0.f;
    for (int r = 0; r < rows_per_block; ++r) acc += X[(size_t)(r0 + r) * DIM + c];
    part[blockIdx.x * DIM + c] = acc;
}

__global__ void colsum_combine(const float* __restrict__ part, int nparts, float scale,
                               float* __restrict__ out) {
    int c = threadIdx.x;
    float acc = 0.f;
    for (int b = 0; b < nparts; ++b) acc += part[b * DIM + c];
    out[c] = acc * scale;
}

// ------------------------- 23x23 SAME conv + bias + leaky_relu, packed f32x2 -------------------------
// R3 inner loop (46 regs), quartered tiles: 16 output rows/block, 128 threads, grid 1024.
// block (64,2): thread -> 1 column-pair (c, c+64), 8 output rows.
#define SPITCH 88
#define TROWS  38   // 16 + 22 halo
__global__ void __launch_bounds__(128) conv_leaky(const float* __restrict__ in,
                                                  float* __restrict__ out,
                                                  const float* __restrict__ kw,
                                                  const float* __restrict__ kb) {
    __shared__ float2 s_in2[TROWS * SPITCH];
    __shared__ float2 s_k2[CK * CK];
    int tid = threadIdx.x + threadIdx.y * 64;
    int r0  = blockIdx.x * 16;

    // input tile: rows r0-11 .. r0+26, column-pairs qi=0..85 -> (qi-11, qi+53)
    for (int idx = tid; idx < TROWS * 86; idx += 128) {
        int rr = idx / 86;
        int qi = idx - rr * 86;
        int gr = r0 - 11 + rr;
        int q  = qi - 11;
        float lo = 0.f, hi = 0.f;
        if (gr >= 0 && gr < NWORDS) {
            const float* grow = in + (size_t)gr * DIM;
            if (q >= 0)       lo = grow[q];
            if (q + 64 < 128) hi = grow[q + 64];
        }
        s_in2[rr * SPITCH + qi] = make_float2(lo, hi);
    }
    for (int idx = tid; idx < CK * CK; idx += 128) {
        float w = kw[idx];
        s_k2[idx] = make_float2(w, w);
    }
    __syncthreads();

    float bias = kb[0];
    int cp    = threadIdx.x;       // column pair
    int rbase = threadIdx.y * 8;   // 0 or 8

    u64 acc2[8];
#pragma unroll
    for (int o = 0; o < 8; ++o) acc2[o] = 0ull;

#pragma unroll 1
    for (int dc = 0; dc < CK; ++dc) {
        u64 wc2[CK];
#pragma unroll
        for (int dr = 0; dr < CK; ++dr)
            wc2[dr] = *reinterpret_cast<const u64*>(&s_k2[dr * CK + dc]);

        const u64* col = reinterpret_cast<const u64*>(s_in2) + rbase * SPITCH + cp + dc;
#pragma unroll
        for (int R = 0; R < 30; ++R) {
            u64 v2 = col[R * SPITCH];
#pragma unroll
            for (int dr = 0; dr < CK; ++dr) {
                int o = R - dr;
                if (o >= 0 && o < 8) ffma2(acc2[o], v2, wc2[dr]);
            }
        }
    }

#pragma unroll
    for (int o = 0; o < 8; ++o) {
        int row = r0 + rbase + o;
        float vl = lo32(acc2[o]) + bias;
        float vh = hi32(acc2[o]) + bias;
        out[(size_t)row * DIM + cp]      = vl > 0.f ? vl : 0.01f * vl;
        out[(size_t)row * DIM + cp + 64] = vh > 0.f ? vh : 0.01f * vh;
    }
}

// ------------------------- h = relu(compound @ W_att^T + b) (single row) -------------------------
__global__ void small_linear_relu(const float* __restrict__ xin, const float* __restrict__ W,
                                  const float* __restrict__ b, float* __restrict__ out) {
    __shared__ float sx[DIM];
    int j = threadIdx.x;
    sx[j] = xin[j];
    __syncthreads();
    float acc = b[j];
    for (int k = 0; k < DIM; ++k) acc += sx[k] * W[j * DIM + k];
    out[j] = acc > 0.f ? acc : 0.f;
}

// ------------------------- protein = mean_m tanh(h . hs_m) * hs_m  (partials) -------------------------
__global__ void protein_partial(const float* __restrict__ hs) {
    __shared__ float sh[DIM];
    __shared__ float sacc[4][DIM];
    int tid  = threadIdx.x;
    int lane = tid & 31;
    int w    = tid >> 5;
    sh[tid] = g_hatt[tid];
    __syncthreads();
    float h0 = sh[lane], h1 = sh[lane + 32], h2 = sh[lane + 64], h3 = sh[lane + 96];
    float a0 = 0.f, a1 = 0.f, a2 = 0.f, a3 = 0.f;
    int m0 = blockIdx.x * 128 + w * 32;
    for (int mi = 0; mi < 32; ++mi) {
        const float* row = hs + (size_t)(m0 + mi) * DIM;
        float d = row[lane] * h0 + row[lane + 32] * h1 + row[lane + 64] * h2 + row[lane + 96] * h3;
#pragma unroll
        for (int off = 16; off; off >>= 1) d += __shfl_xor_sync(0xffffffffu, d, off);
        float t = tanhf(d);
        float4 v = *reinterpret_cast<const float4*>(row + lane * 4);
        a0 += t * v.x;
        a1 += t * v.y;
        a2 += t * v.z;
        a3 += t * v.w;
    }
    sacc[w][lane * 4 + 0] = a0;
    sacc[w][lane * 4 + 1] = a1;
    sacc[w][lane * 4 + 2] = a2;
    sacc[w][lane * 4 + 3] = a3;
    __syncthreads();
    g_part[blockIdx.x * DIM + tid] =
        sacc[0][tid] + sacc[1][tid] + sacc[2][tid] + sacc[3][tid];
}

// ------------------------- final 2-layer MLP + scalar head (coalesced) -------------------------
__global__ void final_mlp(const float* __restrict__ Wout, const float* __restrict__ bout,
                          const float* __restrict__ Wint, const float* __restrict__ bint,
                          float* __restrict__ out) {
    __shared__ float cat[256];
    __shared__ float nxt[256];
    __shared__ float red[256];
    int t = threadIdx.x;          // 256
    int lane = t & 31, w = t >> 5;
    if (t < 128) {
        cat[t]       = g_compound[t];
        cat[t + 128] = g_protein[t];
    }
    __syncthreads();
    for (int l = 0; l < 2; ++l) {
        const float* Wl = Wout + l * 256 * 256;
        // warp w computes outputs j = w*32 .. w*32+31; lanes split k (coalesced rows)
#pragma unroll 1
        for (int jj = 0; jj < 32; ++jj) {
            int j = w * 32 + jj;
            const float* row = Wl + j * 256;
            float s = 0.f;
#pragma unroll
            for (int i = 0; i < 8; ++i) s += cat[lane + i * 32] * row[lane + i * 32];
#pragma unroll
            for (int off = 16; off; off >>= 1) s += __shfl_xor_sync(0xffffffffu, s, off);
            if (lane == 0) {
                float v = s + bout[l * 256 + j];
                nxt[j] = v > 0.f ? v : 0.f;
            }
        }
        __syncthreads();
        cat[t] = nxt[t];
        __syncthreads();
    }
    red[t] = cat[t] * Wint[t];
    __syncthreads();
    for (int s = 128; s; s >>= 1) {
        if (t < s) red[t] += red[t + s];
        __syncthreads();
    }
    if (t == 0) out[0] = red[0] + bint[0];
}

// ------------------------- launch -------------------------
extern "C" void kernel_launch(void* const* d_in, const int* in_sizes, int n_in,
                              void* d_out, int out_size) {
    const int*   fingerprints = (const int*)d_in[0];
    const float* adjacency    = (const float*)d_in[1];
    const int*   words        = (const int*)d_in[2];
    const float* emb_fp       = (const float*)d_in[3];
    const float* emb_word     = (const float*)d_in[4];
    const float* W_gnn_w      = (const float*)d_in[5];
    const float* W_gnn_b      = (const float*)d_in[6];
    const float* conv_w       = (const float*)d_in[7];
    const float* conv_b       = (const float*)d_in[8];
    const float* W_att_w      = (const float*)d_in[9];
    const float* W_att_b      = (const float*)d_in[10];
    const float* W_out_w      = (const float*)d_in[11];
    const float* W_out_b      = (const float*)d_in[12];
    const float* W_int_w      = (const float*)d_in[13];
    const float* W_int_b      = (const float*)d_in[14];
    float* out = (float*)d_out;

    float *xs, *hs, *imgA, *imgB, *hsatt, *part, *comp, *hatt, *prot;
    cudaGetSymbolAddress((void**)&xs,    g_xs);
    cudaGetSymbolAddress((void**)&hs,    g_hs);
    cudaGetSymbolAddress((void**)&imgA,  g_imgA);
    cudaGetSymbolAddress((void**)&imgB,  g_imgB);
    cudaGetSymbolAddress((void**)&hsatt, g_hsatt);
    cudaGetSymbolAddress((void**)&part,  g_part);
    cudaGetSymbolAddress((void**)&comp,  g_compound);
    cudaGetSymbolAddress((void**)&hatt,  g_hatt);
    cudaGetSymbolAddress((void**)&prot,  g_protein);

    int smem_lin = (128 * 129 + 32 * 128) * (int)sizeof(float);
    cudaFuncSetAttribute(linear_relu, cudaFuncAttributeMaxDynamicSharedMemorySize, smem_lin);

    // ---- protein branch first (ncu -s 5 -c 1 lands on conv3 = launch #6) ----
    gather_kernel<<<(NA * DIM + 255) / 256, 256>>>(fingerprints, emb_fp, xs, NA);       // 1
    build_nz<<<NA / 8, 256>>>(adjacency);                                               // 2
    gather_kernel<<<(NWORDS * DIM + 255) / 256, 256>>>(words, emb_word, imgA, NWORDS);  // 3
    conv_leaky<<<NWORDS / 16, dim3(64, 2)>>>(imgA, imgB, conv_w + 0 * CK * CK, conv_b + 0); // 4
    conv_leaky<<<NWORDS / 16, dim3(64, 2)>>>(imgB, imgA, conv_w + 1 * CK * CK, conv_b + 1); // 5
    conv_leaky<<<NWORDS / 16, dim3(64, 2)>>>(imgA, imgB, conv_w + 2 * CK * CK, conv_b + 2); // 6

    // ---- compound (GNN) ----
    for (int l = 0; l < 3; ++l) {
        linear_relu<<<NA / 32, 256, smem_lin>>>(xs, W_gnn_w + l * DIM * DIM,
                                                W_gnn_b + l * DIM, hs);
        spmm_add<<<NA / 8, 256>>>(hs);
    }
    colsum_partial<<<32, 128>>>(xs, part, NA / 32);
    colsum_combine<<<1, 128>>>(part, 32, 1.0f / NA, comp);

    // ---- protein attention ----
    linear_relu<<<NWORDS / 32, 256, smem_lin>>>(imgB, W_att_w, W_att_b, hsatt);
    small_linear_relu<<<1, 128>>>(comp, W_att_w, W_att_b, hatt);
    protein_partial<<<NWORDS / 128, 128>>>(hsatt);
    colsum_combine<<<1, 128>>>(part, 128, 1.0f / NWORDS, prot);

    // ---- head ----
    final_mlp<<<1, 256>>>(W_out_w, W_out_b, W_int_w, W_int_b, out);
}

// round 8
// speedup vs baseline: 1.1743x; 1.0683x over previous
#include <cuda_runtime.h>
#include <math.h>

#define NA     4096
#define NWORDS 16384
#define DIM    128
#define NZCAP  256
#define CK     23

// ------------------------- scratch (no allocations allowed) -------------------------
__device__ float g_xs[NA * DIM];
__device__ float g_hs[NA * DIM];
__device__ int   g_nzidx[NA * NZCAP];
__device__ int   g_nzcnt[NA];
__device__ float g_imgA[NWORDS * DIM];
__device__ float g_imgB[NWORDS * DIM];
__device__ float g_hsatt[NWORDS * DIM];
__device__ float g_part[128 * DIM];
__device__ float g_compound[DIM];
__device__ float g_hatt[DIM];

// ------------------------- f32x2 helpers -------------------------
typedef unsigned long long u64;
__device__ __forceinline__ void ffma2(u64& d, u64 a, u64 b) {
    asm("fma.rn.f32x2 %0, %1, %2, %0;" : "+l"(d) : "l"(a), "l"(b));
}
__device__ __forceinline__ u64 dup2(float w) {
    u64 r;
    asm("mov.b64 %0, {%1, %1};" : "=l"(r) : "r"(__float_as_uint(w)));
    return r;
}
__device__ __forceinline__ float lo32(u64 v) {
    return __uint_as_float((unsigned)(v & 0xffffffffull));
}
__device__ __forceinline__ float hi32(u64 v) {
    return __uint_as_float((unsigned)(v >> 32));
}

// ------------------------- sparse adjacency build (deterministic, ordered) -------------------------
__global__ void build_nz(const float* __restrict__ adj) {
    int warp = (blockIdx.x * blockDim.x + threadIdx.x) >> 5;
    int lane = threadIdx.x & 31;
    if (warp >= NA) return;
    const float* row = adj + (size_t)warp * NA;
    int base = 0;
    for (int j0 = 0; j0 < NA; j0 += 32) {
        float v = row[j0 + lane];
        unsigned mask = __ballot_sync(0xffffffffu, v != 0.f);
        if (v != 0.f) {
            int r = __popc(mask & ((1u << lane) - 1));
            int p = base + r;
            if (p < NZCAP) g_nzidx[warp * NZCAP + p] = j0 + lane;
        }
        base += __popc(mask);
    }
    if (lane == 0) g_nzcnt[warp] = base < NZCAP ? base : NZCAP;
}

// ------------------------- Y = relu(X @ W^T + b), N=K=128, f32x2 core -------------------------
// Optional inline gather (gidx/gemb) for layer-0; optionally mirrors gathered X to Xout.
__global__ void __launch_bounds__(256) linear_relu(const float* __restrict__ X,
                                                   const float* __restrict__ W,
                                                   const float* __restrict__ b,
                                                   float* __restrict__ Y,
                                                   const int* __restrict__ gidx,
                                                   const float* __restrict__ gemb,
                                                   float* __restrict__ Xout) {
    extern __shared__ float sm[];
    float*  sW  = sm;                          // [128][129]
    float2* sXP = (float2*)(sm + 128 * 129);   // [16][128] row pairs
    int tid = threadIdx.x;
    for (int idx = tid; idx < 128 * 128; idx += 256) {
        int j = idx >> 7, k = idx & 127;
        sW[j * 129 + k] = W[idx];
    }
    int r0 = blockIdx.x * 32;
    for (int idx = tid; idx < 16 * 128; idx += 256) {
        int p = idx >> 7, k = idx & 127;
        int row0 = r0 + 2 * p;
        float x0, x1;
        if (gidx) {
            x0 = gemb[(size_t)gidx[row0] * DIM + k];
            x1 = gemb[(size_t)gidx[row0 + 1] * DIM + k];
            Xout[(size_t)row0 * DIM + k]       = x0;
            Xout[(size_t)(row0 + 1) * DIM + k] = x1;
        } else {
            x0 = X[(size_t)row0 * DIM + k];
            x1 = X[(size_t)(row0 + 1) * DIM + k];
        }
        sXP[p * 128 + k] = make_float2(x0, x1);
    }
    __syncthreads();

    int lane = tid & 31;
    int rg   = tid >> 5;        // warp-uniform
    int i0   = rg * 4;
    const u64* sxp = reinterpret_cast<const u64*>(sXP);
    const u64* pA  = sxp + (rg * 2) * 128;
    const u64* pB  = sxp + (rg * 2 + 1) * 128;

    u64 accA[4], accB[4];
#pragma unroll
    for (int q = 0; q < 4; ++q) { accA[q] = 0ull; accB[q] = 0ull; }

#pragma unroll 4
    for (int k = 0; k < 128; ++k) {
        u64 a01 = pA[k];   // (X[i0][k],   X[i0+1][k])
        u64 a23 = pB[k];   // (X[i0+2][k], X[i0+3][k])
#pragma unroll
        for (int q = 0; q < 4; ++q) {
            u64 ww = dup2(sW[(lane + q * 32) * 129 + k]);
            ffma2(accA[q], a01, ww);
            ffma2(accB[q], a23, ww);
        }
    }
#pragma unroll
    for (int q = 0; q < 4; ++q) {
        int j = lane + q * 32;
        float bj = b[j];
        float v0 = lo32(accA[q]) + bj;
        float v1 = hi32(accA[q]) + bj;
        float v2 = lo32(accB[q]) + bj;
        float v3 = hi32(accB[q]) + bj;
        Y[(size_t)(r0 + i0 + 0) * DIM + j] = v0 > 0.f ? v0 : 0.f;
        Y[(size_t)(r0 + i0 + 1) * DIM + j] = v1 > 0.f ? v1 : 0.f;
        Y[(size_t)(r0 + i0 + 2) * DIM + j] = v2 > 0.f ? v2 : 0.f;
        Y[(size_t)(r0 + i0 + 3) * DIM + j] = v3 > 0.f ? v3 : 0.f;
    }
}

// ------------------------- xs += A_sparse @ hs (warp-per-row, float4 lanes) -------------------------
__global__ void __launch_bounds__(256) spmm_add(const float* __restrict__ hs) {
    int row  = blockIdx.x * 8 + (threadIdx.x >> 5);
    int lane = threadIdx.x & 31;
    int cnt = g_nzcnt[row];
    const int* nz = g_nzidx + row * NZCAP;

    float4 a0 = make_float4(0.f, 0.f, 0.f, 0.f);
    float4 a1 = make_float4(0.f, 0.f, 0.f, 0.f);
    int t = 0;
    for (; t + 2 <= cnt; t += 2) {
        int j0 = nz[t], j1 = nz[t + 1];
        float4 v0 = *reinterpret_cast<const float4*>(hs + (size_t)j0 * DIM + lane * 4);
        float4 v1 = *reinterpret_cast<const float4*>(hs + (size_t)j1 * DIM + lane * 4);
        a0.x += v0.x; a0.y += v0.y; a0.z += v0.z; a0.w += v0.w;
        a1.x += v1.x; a1.y += v1.y; a1.z += v1.z; a1.w += v1.w;
    }
    if (t < cnt) {
        float4 v0 = *reinterpret_cast<const float4*>(hs + (size_t)nz[t] * DIM + lane * 4);
        a0.x += v0.x; a0.y += v0.y; a0.z += v0.z; a0.w += v0.w;
    }
    float4* dst = reinterpret_cast<float4*>(g_xs + (size_t)row * DIM + lane * 4);
    float4 x = *dst;
    x.x += a0.x + a1.x;
    x.y += a0.y + a1.y;
    x.z += a0.z + a1.z;
    x.w += a0.w + a1.w;
    *dst = x;
}

// ------------------------- column-sum partials -------------------------
__global__ void colsum_partial(const float* __restrict__ X, float* __restrict__ part,
                               int rows_per_block) {
    int c = threadIdx.x;
    int r0 = blockIdx.x * rows_per_block;
    float acc = 0.f;
    for (int r = 0; r < rows_per_block; ++r) acc += X[(size_t)(r0 + r) * DIM + c];
    part[blockIdx.x * DIM + c] = acc;
}

// ------------------------- 23x23 SAME conv + bias + leaky_relu, packed f32x2 -------------------------
// Proven R7 body. Optional inline word-embedding gather (widx/wemb) for layer 1.
#define SPITCH 88
#define TROWS  38   // 16 + 22 halo
__global__ void __launch_bounds__(128) conv_leaky(const float* __restrict__ in,
                                                  float* __restrict__ out,
                                                  const float* __restrict__ kw,
                                                  const float* __restrict__ kb,
                                                  const int* __restrict__ widx,
                                                  const float* __restrict__ wemb) {
    __shared__ float2 s_in2[TROWS * SPITCH];
    __shared__ float2 s_k2[CK * CK];
    int tid = threadIdx.x + threadIdx.y * 64;
    int r0  = blockIdx.x * 16;

    for (int idx = tid; idx < TROWS * 86; idx += 128) {
        int rr = idx / 86;
        int qi = idx - rr * 86;
        int gr = r0 - 11 + rr;
        int q  = qi - 11;
        float lo = 0.f, hi = 0.f;
        if (gr >= 0 && gr < NWORDS) {
            const float* grow = widx ? (wemb + (size_t)widx[gr] * DIM)
                                     : (in + (size_t)gr * DIM);
            if (q >= 0)       lo = grow[q];
            if (q + 64 < 128) hi = grow[q + 64];
        }
        s_in2[rr * SPITCH + qi] = make_float2(lo, hi);
    }
    for (int idx = tid; idx < CK * CK; idx += 128) {
        float w = kw[idx];
        s_k2[idx] = make_float2(w, w);
    }
    __syncthreads();

    float bias = kb[0];
    int cp    = threadIdx.x;
    int rbase = threadIdx.y * 8;

    u64 acc2[8];
#pragma unroll
    for (int o = 0; o < 8; ++o) acc2[o] = 0ull;

#pragma unroll 1
    for (int dc = 0; dc < CK; ++dc) {
        u64 wc2[CK];
#pragma unroll
        for (int dr = 0; dr < CK; ++dr)
            wc2[dr] = *reinterpret_cast<const u64*>(&s_k2[dr * CK + dc]);

        const u64* col = reinterpret_cast<const u64*>(s_in2) + rbase * SPITCH + cp + dc;
#pragma unroll
        for (int R = 0; R < 30; ++R) {
            u64 v2 = col[R * SPITCH];
#pragma unroll
            for (int dr = 0; dr < CK; ++dr) {
                int o = R - dr;
                if (o >= 0 && o < 8) ffma2(acc2[o], v2, wc2[dr]);
            }
        }
    }

#pragma unroll
    for (int o = 0; o < 8; ++o) {
        int row = r0 + rbase + o;
        float vl = lo32(acc2[o]) + bias;
        float vh = hi32(acc2[o]) + bias;
        out[(size_t)row * DIM + cp]      = vl > 0.f ? vl : 0.01f * vl;
        out[(size_t)row * DIM + cp + 64] = vh > 0.f ? vh : 0.01f * vh;
    }
}

// ------------------------- fused: GNN combine -> compound -> h_att -------------------------
__global__ void comb_att(const float* __restrict__ part, const float* __restrict__ W,
                         const float* __restrict__ b) {
    __shared__ float sc[DIM];
    int j = threadIdx.x;   // 128
    float acc = 0.f;
    for (int i = 0; i < 32; ++i) acc += part[i * DIM + j];
    float compv = acc * (1.0f / NA);
    g_compound[j] = compv;
    sc[j] = compv;
    __syncthreads();
    float h = b[j];
    for (int k = 0; k < DIM; ++k) h += sc[k] * W[j * DIM + k];
    g_hatt[j] = h > 0.f ? h : 0.f;
}

// ------------------------- protein = mean_m tanh(h . hs_m) * hs_m  (partials) -------------------------
__global__ void protein_partial(const float* __restrict__ hs) {
    __shared__ float sh[DIM];
    __shared__ float sacc[4][DIM];
    int tid  = threadIdx.x;
    int lane = tid & 31;
    int w    = tid >> 5;
    sh[tid] = g_hatt[tid];
    __syncthreads();
    float h0 = sh[lane], h1 = sh[lane + 32], h2 = sh[lane + 64], h3 = sh[lane + 96];
    float a0 = 0.f, a1 = 0.f, a2 = 0.f, a3 = 0.f;
    int m0 = blockIdx.x * 128 + w * 32;
    for (int mi = 0; mi < 32; ++mi) {
        const float* row = hs + (size_t)(m0 + mi) * DIM;
        float d = row[lane] * h0 + row[lane + 32] * h1 + row[lane + 64] * h2 + row[lane + 96] * h3;
#pragma unroll
        for (int off = 16; off; off >>= 1) d += __shfl_xor_sync(0xffffffffu, d, off);
        float t = tanhf(d);
        float4 v = *reinterpret_cast<const float4*>(row + lane * 4);
        a0 += t * v.x;
        a1 += t * v.y;
        a2 += t * v.z;
        a3 += t * v.w;
    }
    sacc[w][lane * 4 + 0] = a0;
    sacc[w][lane * 4 + 1] = a1;
    sacc[w][lane * 4 + 2] = a2;
    sacc[w][lane * 4 + 3] = a3;
    __syncthreads();
    g_part[blockIdx.x * DIM + tid] =
        sacc[0][tid] + sacc[1][tid] + sacc[2][tid] + sacc[3][tid];
}

// ------------------------- fused: protein combine + 2-layer MLP + scalar head -------------------------
__global__ void final_mlp(const float* __restrict__ part,
                          const float* __restrict__ Wout, const float* __restrict__ bout,
                          const float* __restrict__ Wint, const float* __restrict__ bint,
                          float* __restrict__ out) {
    __shared__ float cat[256];
    __shared__ float nxt[256];
    __shared__ float red[256];
    int t = threadIdx.x;          // 256
    int lane = t & 31, w = t >> 5;
    if (t < 128) {
        float s = 0.f;
        for (int i = 0; i < 128; ++i) s += part[i * DIM + t];
        cat[t + 128] = s * (1.0f / NWORDS);   // protein
        cat[t]       = g_compound[t];
    }
    __syncthreads();
    for (int l = 0; l < 2; ++l) {
        const float* Wl = Wout + l * 256 * 256;
#pragma unroll 1
        for (int jj = 0; jj < 32; ++jj) {
            int j = w * 32 + jj;
            const float* row = Wl + j * 256;
            float s = 0.f;
#pragma unroll
            for (int i = 0; i < 8; ++i) s += cat[lane + i * 32] * row[lane + i * 32];
#pragma unroll
            for (int off = 16; off; off >>= 1) s += __shfl_xor_sync(0xffffffffu, s, off);
            if (lane == 0) {
                float v = s + bout[l * 256 + j];
                nxt[j] = v > 0.f ? v : 0.f;
            }
        }
        __syncthreads();
        cat[t] = nxt[t];
        __syncthreads();
    }
    red[t] = cat[t] * Wint[t];
    __syncthreads();
    for (int s = 128; s; s >>= 1) {
        if (t < s) red[t] += red[t + s];
        __syncthreads();
    }
    if (t == 0) out[0] = red[0] + bint[0];
}

// ------------------------- launch -------------------------
extern "C" void kernel_launch(void* const* d_in, const int* in_sizes, int n_in,
                              void* d_out, int out_size) {
    const int*   fingerprints = (const int*)d_in[0];
    const float* adjacency    = (const float*)d_in[1];
    const int*   words        = (const int*)d_in[2];
    const float* emb_fp       = (const float*)d_in[3];
    const float* emb_word     = (const float*)d_in[4];
    const float* W_gnn_w      = (const float*)d_in[5];
    const float* W_gnn_b      = (const float*)d_in[6];
    const float* conv_w       = (const float*)d_in[7];
    const float* conv_b       = (const float*)d_in[8];
    const float* W_att_w      = (const float*)d_in[9];
    const float* W_att_b      = (const float*)d_in[10];
    const float* W_out_w      = (const float*)d_in[11];
    const float* W_out_b      = (const float*)d_in[12];
    const float* W_int_w      = (const float*)d_in[13];
    const float* W_int_b      = (const float*)d_in[14];
    float* out = (float*)d_out;

    float *xs, *hs, *imgA, *imgB, *hsatt, *part;
    cudaGetSymbolAddress((void**)&xs,    g_xs);
    cudaGetSymbolAddress((void**)&hs,    g_hs);
    cudaGetSymbolAddress((void**)&imgA,  g_imgA);
    cudaGetSymbolAddress((void**)&imgB,  g_imgB);
    cudaGetSymbolAddress((void**)&hsatt, g_hsatt);
    cudaGetSymbolAddress((void**)&part,  g_part);

    int smem_lin = (128 * 129 + 16 * 256) * (int)sizeof(float);
    cudaFuncSetAttribute(linear_relu, cudaFuncAttributeMaxDynamicSharedMemorySize, smem_lin);

    // 1: conv layer 1 with inline word-embedding gather
    conv_leaky<<<NWORDS / 16, dim3(64, 2)>>>(imgB, imgA, conv_w + 0 * CK * CK, conv_b + 0,
                                             words, emb_word);
    // 2: conv layer 2
    conv_leaky<<<NWORDS / 16, dim3(64, 2)>>>(imgA, imgB, conv_w + 1 * CK * CK, conv_b + 1,
                                             (const int*)0, (const float*)0);
    // 3: adjacency CSR build
    build_nz<<<NA / 8, 256>>>(adjacency);
    // 4: GNN layer 0 linear with inline fingerprint gather (also materializes xs)
    linear_relu<<<NA / 32, 256, smem_lin>>>((const float*)0, W_gnn_w + 0, W_gnn_b + 0, hs,
                                            fingerprints, emb_fp, xs);
    // 5: GNN spmm 0
    spmm_add<<<NA / 8, 256>>>(hs);
    // 6: conv layer 3  <-- ncu -s 5 -c 1 profiles this launch
    conv_leaky<<<NWORDS / 16, dim3(64, 2)>>>(imgB, imgA, conv_w + 2 * CK * CK, conv_b + 2,
                                             (const int*)0, (const float*)0);

    // GNN layers 1..2
    for (int l = 1; l < 3; ++l) {
        linear_relu<<<NA / 32, 256, smem_lin>>>(xs, W_gnn_w + l * DIM * DIM,
                                                W_gnn_b + l * DIM, hs,
                                                (const int*)0, (const float*)0, (float*)0);
        spmm_add<<<NA / 8, 256>>>(hs);
    }
    colsum_partial<<<32, 128>>>(xs, part, NA / 32);

    // protein attention linear (conv output lives in imgA after 3 layers)
    linear_relu<<<NWORDS / 32, 256, smem_lin>>>(imgA, W_att_w, W_att_b, hsatt,
                                                (const int*)0, (const float*)0, (float*)0);
    // compound combine + h_att
    comb_att<<<1, 128>>>(part, W_att_w, W_att_b);
    // attention partials
    protein_partial<<<NWORDS / 128, 128>>>(hsatt);
    // protein combine + output head
    final_mlp<<<1, 256>>>(part, W_out_w, W_out_b, W_int_w, W_int_b, out);
}

// round 9
// speedup vs baseline: 1.3953x; 1.1882x over previous
#include <cuda_runtime.h>
#include <math.h>

#define NA     4096
#define NWORDS 16384
#define DIM    128
#define NZCAP  256
#define CK     23

// ------------------------- scratch (no allocations allowed) -------------------------
__device__ float g_xs[NA * DIM];
__device__ float g_hs[NA * DIM];
__device__ int   g_nzidx[NA * NZCAP];
__device__ int   g_nzcnt[NA];
__device__ float g_imgA[NWORDS * DIM];
__device__ float g_imgB[NWORDS * DIM];
__device__ float g_hsatt[NWORDS * DIM];
__device__ float g_part[256 * DIM];
__device__ float g_compound[DIM];
__device__ float g_hatt[DIM];

// ------------------------- f32x2 helpers -------------------------
typedef unsigned long long u64;
__device__ __forceinline__ void ffma2(u64& d, u64 a, u64 b) {
    asm("fma.rn.f32x2 %0, %1, %2, %0;" : "+l"(d) : "l"(a), "l"(b));
}
__device__ __forceinline__ u64 dup2(float w) {
    u64 r;
    asm("mov.b64 %0, {%1, %1};" : "=l"(r) : "r"(__float_as_uint(w)));
    return r;
}
__device__ __forceinline__ float lo32(u64 v) {
    return __uint_as_float((unsigned)(v & 0xffffffffull));
}
__device__ __forceinline__ float hi32(u64 v) {
    return __uint_as_float((unsigned)(v >> 32));
}

// ------------------------- sparse adjacency build (deterministic, ordered) -------------------------
__global__ void build_nz(const float* __restrict__ adj) {
    int warp = (blockIdx.x * blockDim.x + threadIdx.x) >> 5;
    int lane = threadIdx.x & 31;
    if (warp >= NA) return;
    const float* row = adj + (size_t)warp * NA;
    int base = 0;
    for (int j0 = 0; j0 < NA; j0 += 32) {
        float v = row[j0 + lane];
        unsigned mask = __ballot_sync(0xffffffffu, v != 0.f);
        if (v != 0.f) {
            int r = __popc(mask & ((1u << lane) - 1));
            int p = base + r;
            if (p < NZCAP) g_nzidx[warp * NZCAP + p] = j0 + lane;
        }
        base += __popc(mask);
    }
    if (lane == 0) g_nzcnt[warp] = base < NZCAP ? base : NZCAP;
}

// ------------------------- Y = relu(X @ W^T + b), col-split f32x2 -------------------------
// block: 256 threads, 32 rows x 64 output cols (blockIdx.y = col half).
// Identical k-order per output as before -> bitwise identical results.
__global__ void __launch_bounds__(256) linear_relu(const float* __restrict__ X,
                                                   const float* __restrict__ W,
                                                   const float* __restrict__ b,
                                                   float* __restrict__ Y,
                                                   const int* __restrict__ gidx,
                                                   const float* __restrict__ gemb,
                                                   float* __restrict__ Xout) {
    extern __shared__ float sm[];
    float*  sW  = sm;                         // [64][129]
    float2* sXP = (float2*)(sm + 64 * 129);   // [16][128] row pairs
    int tid = threadIdx.x;
    int jh  = blockIdx.y;                     // 0 or 1
    int r0  = blockIdx.x * 32;

    for (int idx = tid; idx < 64 * 128; idx += 256) {
        int j = idx >> 7, k = idx & 127;
        sW[j * 129 + k] = W[(size_t)(jh * 64 + j) * 128 + k];
    }
    for (int idx = tid; idx < 16 * 128; idx += 256) {
        int p = idx >> 7, k = idx & 127;
        int row0 = r0 + 2 * p;
        float x0, x1;
        if (gidx) {
            x0 = gemb[(size_t)gidx[row0] * DIM + k];
            x1 = gemb[(size_t)gidx[row0 + 1] * DIM + k];
            if (jh == 0) {
                Xout[(size_t)row0 * DIM + k]       = x0;
                Xout[(size_t)(row0 + 1) * DIM + k] = x1;
            }
        } else {
            x0 = X[(size_t)row0 * DIM + k];
            x1 = X[(size_t)(row0 + 1) * DIM + k];
        }
        sXP[p * 128 + k] = make_float2(x0, x1);
    }
    __syncthreads();

    int lane = tid & 31;
    int rg   = tid >> 5;        // warp-uniform
    int i0   = rg * 4;
    const u64* sxp = reinterpret_cast<const u64*>(sXP);
    const u64* pA  = sxp + (rg * 2) * 128;
    const u64* pB  = sxp + (rg * 2 + 1) * 128;

    u64 accA[2], accB[2];
#pragma unroll
    for (int q = 0; q < 2; ++q) { accA[q] = 0ull; accB[q] = 0ull; }

#pragma unroll 4
    for (int k = 0; k < 128; ++k) {
        u64 a01 = pA[k];
        u64 a23 = pB[k];
#pragma unroll
        for (int q = 0; q < 2; ++q) {
            u64 ww = dup2(sW[(lane + q * 32) * 129 + k]);
            ffma2(accA[q], a01, ww);
            ffma2(accB[q], a23, ww);
        }
    }
#pragma unroll
    for (int q = 0; q < 2; ++q) {
        int j = jh * 64 + lane + q * 32;
        float bj = b[j];
        float v0 = lo32(accA[q]) + bj;
        float v1 = hi32(accA[q]) + bj;
        float v2 = lo32(accB[q]) + bj;
        float v3 = hi32(accB[q]) + bj;
        Y[(size_t)(r0 + i0 + 0) * DIM + j] = v0 > 0.f ? v0 : 0.f;
        Y[(size_t)(r0 + i0 + 1) * DIM + j] = v1 > 0.f ? v1 : 0.f;
        Y[(size_t)(r0 + i0 + 2) * DIM + j] = v2 > 0.f ? v2 : 0.f;
        Y[(size_t)(r0 + i0 + 3) * DIM + j] = v3 > 0.f ? v3 : 0.f;
    }
}

// ------------------------- xs += A_sparse @ hs (warp-per-row, float4 lanes) -------------------------
__global__ void __launch_bounds__(256) spmm_add(const float* __restrict__ hs) {
    int row  = blockIdx.x * 8 + (threadIdx.x >> 5);
    int lane = threadIdx.x & 31;
    int cnt = g_nzcnt[row];
    const int* nz = g_nzidx + row * NZCAP;

    float4 a0 = make_float4(0.f, 0.f, 0.f, 0.f);
    float4 a1 = make_float4(0.f, 0.f, 0.f, 0.f);
    int t = 0;
    for (; t + 2 <= cnt; t += 2) {
        int j0 = nz[t], j1 = nz[t + 1];
        float4 v0 = *reinterpret_cast<const float4*>(hs + (size_t)j0 * DIM + lane * 4);
        float4 v1 = *reinterpret_cast<const float4*>(hs + (size_t)j1 * DIM + lane * 4);
        a0.x += v0.x; a0.y += v0.y; a0.z += v0.z; a0.w += v0.w;
        a1.x += v1.x; a1.y += v1.y; a1.z += v1.z; a1.w += v1.w;
    }
    if (t < cnt) {
        float4 v0 = *reinterpret_cast<const float4*>(hs + (size_t)nz[t] * DIM + lane * 4);
        a0.x += v0.x; a0.y += v0.y; a0.z += v0.z; a0.w += v0.w;
    }
    float4* dst = reinterpret_cast<float4*>(g_xs + (size_t)row * DIM + lane * 4);
    float4 x = *dst;
    x.x += a0.x + a1.x;
    x.y += a0.y + a1.y;
    x.z += a0.z + a1.z;
    x.w += a0.w + a1.w;
    *dst = x;
}

// ------------------------- column-sum partials -------------------------
__global__ void colsum_partial(const float* __restrict__ X, float* __restrict__ part,
                               int rows_per_block) {
    int c = threadIdx.x;
    int r0 = blockIdx.x * rows_per_block;
    float acc = 0.f;
    for (int r = 0; r < rows_per_block; ++r) acc += X[(size_t)(r0 + r) * DIM + c];
    part[blockIdx.x * DIM + c] = acc;
}

// ------------------------- 23x23 SAME conv + bias + leaky_relu, packed f32x2 -------------------------
#define SPITCH 88
#define TROWS  38   // 16 + 22 halo
__global__ void __launch_bounds__(128) conv_leaky(const float* __restrict__ in,
                                                  float* __restrict__ out,
                                                  const float* __restrict__ kw,
                                                  const float* __restrict__ kb,
                                                  const int* __restrict__ widx,
                                                  const float* __restrict__ wemb) {
    __shared__ float2 s_in2[TROWS * SPITCH];
    __shared__ float2 s_k2[CK * CK];
    int tid = threadIdx.x + threadIdx.y * 64;
    int r0  = blockIdx.x * 16;

    for (int idx = tid; idx < TROWS * 86; idx += 128) {
        int rr = idx / 86;
        int qi = idx - rr * 86;
        int gr = r0 - 11 + rr;
        int q  = qi - 11;
        float lo = 0.f, hi = 0.f;
        if (gr >= 0 && gr < NWORDS) {
            const float* grow = widx ? (wemb + (size_t)widx[gr] * DIM)
                                     : (in + (size_t)gr * DIM);
            if (q >= 0)       lo = grow[q];
            if (q + 64 < 128) hi = grow[q + 64];
        }
        s_in2[rr * SPITCH + qi] = make_float2(lo, hi);
    }
    for (int idx = tid; idx < CK * CK; idx += 128) {
        float w = kw[idx];
        s_k2[idx] = make_float2(w, w);
    }
    __syncthreads();

    float bias = kb[0];
    int cp    = threadIdx.x;
    int rbase = threadIdx.y * 8;

    u64 acc2[8];
#pragma unroll
    for (int o = 0; o < 8; ++o) acc2[o] = 0ull;

#pragma unroll 1
    for (int dc = 0; dc < CK; ++dc) {
        u64 wc2[CK];
#pragma unroll
        for (int dr = 0; dr < CK; ++dr)
            wc2[dr] = *reinterpret_cast<const u64*>(&s_k2[dr * CK + dc]);

        const u64* col = reinterpret_cast<const u64*>(s_in2) + rbase * SPITCH + cp + dc;
#pragma unroll
        for (int R = 0; R < 30; ++R) {
            u64 v2 = col[R * SPITCH];
#pragma unroll
            for (int dr = 0; dr < CK; ++dr) {
                int o = R - dr;
                if (o >= 0 && o < 8) ffma2(acc2[o], v2, wc2[dr]);
            }
        }
    }

#pragma unroll
    for (int o = 0; o < 8; ++o) {
        int row = r0 + rbase + o;
        float vl = lo32(acc2[o]) + bias;
        float vh = hi32(acc2[o]) + bias;
        out[(size_t)row * DIM + cp]      = vl > 0.f ? vl : 0.01f * vl;
        out[(size_t)row * DIM + cp + 64] = vh > 0.f ? vh : 0.01f * vh;
    }
}

// ------------------------- fused: GNN combine -> compound -> h_att -------------------------
__global__ void comb_att(const float* __restrict__ part, const float* __restrict__ W,
                         const float* __restrict__ b) {
    __shared__ float sc[DIM];
    int j = threadIdx.x;   // 128
    float acc = 0.f;
    for (int i = 0; i < 32; ++i) acc += part[i * DIM + j];
    float compv = acc * (1.0f / NA);
    g_compound[j] = compv;
    sc[j] = compv;
    __syncthreads();
    float h = b[j];
    for (int k = 0; k < DIM; ++k) h += sc[k] * W[j * DIM + k];
    g_hatt[j] = h > 0.f ? h : 0.f;
}

// ------------------------- protein attention partials (grid 256, 64 rows/block) -------------------------
__global__ void protein_partial(const float* __restrict__ hs) {
    __shared__ float sh[DIM];
    __shared__ float sacc[4][DIM];
    int tid  = threadIdx.x;
    int lane = tid & 31;
    int w    = tid >> 5;
    sh[tid] = g_hatt[tid];
    __syncthreads();
    float h0 = sh[lane], h1 = sh[lane + 32], h2 = sh[lane + 64], h3 = sh[lane + 96];
    float a0 = 0.f, a1 = 0.f, a2 = 0.f, a3 = 0.f;
    int m0 = blockIdx.x * 64 + w * 16;
    for (int mi = 0; mi < 16; ++mi) {
        const float* row = hs + (size_t)(m0 + mi) * DIM;
        float d = row[lane] * h0 + row[lane + 32] * h1 + row[lane + 64] * h2 + row[lane + 96] * h3;
#pragma unroll
        for (int off = 16; off; off >>= 1) d += __shfl_xor_sync(0xffffffffu, d, off);
        float t = tanhf(d);
        float4 v = *reinterpret_cast<const float4*>(row + lane * 4);
        a0 += t * v.x;
        a1 += t * v.y;
        a2 += t * v.z;
        a3 += t * v.w;
    }
    sacc[w][lane * 4 + 0] = a0;
    sacc[w][lane * 4 + 1] = a1;
    sacc[w][lane * 4 + 2] = a2;
    sacc[w][lane * 4 + 3] = a3;
    __syncthreads();
    g_part[blockIdx.x * DIM + tid] =
        (sacc[0][tid] + sacc[1][tid]) + (sacc[2][tid] + sacc[3][tid]);
}

// ------------------------- fused: protein combine + 2-layer MLP + scalar head -------------------------
__global__ void final_mlp(const float* __restrict__ part,
                          const float* __restrict__ Wout, const float* __restrict__ bout,
                          const float* __restrict__ Wint, const float* __restrict__ bint,
                          float* __restrict__ out) {
    __shared__ float cat[256];
    __shared__ float nxt[256];
    __shared__ float red[256];
    int t = threadIdx.x;          // 256
    int lane = t & 31, w = t >> 5;
    if (t < 128) {
        float s = 0.f;
        for (int i = 0; i < 256; ++i) s += part[i * DIM + t];
        cat[t + 128] = s * (1.0f / NWORDS);   // protein
        cat[t]       = g_compound[t];
    }
    __syncthreads();
    for (int l = 0; l < 2; ++l) {
        const float* Wl = Wout + l * 256 * 256;
#pragma unroll 1
        for (int jj = 0; jj < 32; ++jj) {
            int j = w * 32 + jj;
            const float* row = Wl + j * 256;
            float s = 0.f;
#pragma unroll
            for (int i = 0; i < 8; ++i) s += cat[lane + i * 32] * row[lane + i * 32];
#pragma unroll
            for (int off = 16; off; off >>= 1) s += __shfl_xor_sync(0xffffffffu, s, off);
            if (lane == 0) {
                float v = s + bout[l * 256 + j];
                nxt[j] = v > 0.f ? v : 0.f;
            }
        }
        __syncthreads();
        cat[t] = nxt[t];
        __syncthreads();
    }
    red[t] = cat[t] * Wint[t];
    __syncthreads();
    for (int s = 128; s; s >>= 1) {
        if (t < s) red[t] += red[t + s];
        __syncthreads();
    }
    if (t == 0) out[0] = red[0] + bint[0];
}

// ------------------------- launch -------------------------
extern "C" void kernel_launch(void* const* d_in, const int* in_sizes, int n_in,
                              void* d_out, int out_size) {
    const int*   fingerprints = (const int*)d_in[0];
    const float* adjacency    = (const float*)d_in[1];
    const int*   words        = (const int*)d_in[2];
    const float* emb_fp       = (const float*)d_in[3];
    const float* emb_word     = (const float*)d_in[4];
    const float* W_gnn_w      = (const float*)d_in[5];
    const float* W_gnn_b      = (const float*)d_in[6];
    const float* conv_w       = (const float*)d_in[7];
    const float* conv_b       = (const float*)d_in[8];
    const float* W_att_w      = (const float*)d_in[9];
    const float* W_att_b      = (const float*)d_in[10];
    const float* W_out_w      = (const float*)d_in[11];
    const float* W_out_b      = (const float*)d_in[12];
    const float* W_int_w      = (const float*)d_in[13];
    const float* W_int_b      = (const float*)d_in[14];
    float* out = (float*)d_out;

    float *xs, *hs, *imgA, *imgB, *hsatt, *part;
    cudaGetSymbolAddress((void**)&xs,    g_xs);
    cudaGetSymbolAddress((void**)&hs,    g_hs);
    cudaGetSymbolAddress((void**)&imgA,  g_imgA);
    cudaGetSymbolAddress((void**)&imgB,  g_imgB);
    cudaGetSymbolAddress((void**)&hsatt, g_hsatt);
    cudaGetSymbolAddress((void**)&part,  g_part);

    int smem_lin = (64 * 129 + 16 * 256) * (int)sizeof(float);
    cudaFuncSetAttribute(linear_relu, cudaFuncAttributeMaxDynamicSharedMemorySize, smem_lin);

    // one-time infra (host objects only; no device memory)
    static cudaStream_t s1 = 0, s2 = 0;
    static cudaEvent_t ef = 0, e1 = 0, e2 = 0;
    if (!s1) {
        cudaStreamCreateWithFlags(&s1, cudaStreamNonBlocking);
        cudaStreamCreateWithFlags(&s2, cudaStreamNonBlocking);
        cudaEventCreateWithFlags(&ef, cudaEventDisableTiming);
        cudaEventCreateWithFlags(&e1, cudaEventDisableTiming);
        cudaEventCreateWithFlags(&e2, cudaEventDisableTiming);
    }

    // fork
    cudaEventRecord(ef, 0);
    cudaStreamWaitEvent(s1, ef, 0);
    cudaStreamWaitEvent(s2, ef, 0);

    dim3 linNA(NA / 32, 2), linNW(NWORDS / 32, 2);

    // stream1: conv chain (+ attention linear, which depends only on conv output)
    conv_leaky<<<NWORDS / 16, dim3(64, 2), 0, s1>>>(imgB, imgA, conv_w + 0 * CK * CK,
                                                    conv_b + 0, words, emb_word);      // #1
    conv_leaky<<<NWORDS / 16, dim3(64, 2), 0, s1>>>(imgA, imgB, conv_w + 1 * CK * CK,
                                                    conv_b + 1, (const int*)0, (const float*)0); // #2
    // stream2: GNN chain
    build_nz<<<NA / 8, 256, 0, s2>>>(adjacency);                                       // #3
    linear_relu<<<linNA, 256, smem_lin, s2>>>((const float*)0, W_gnn_w + 0, W_gnn_b + 0,
                                              hs, fingerprints, emb_fp, xs);           // #4
    spmm_add<<<NA / 8, 256, 0, s2>>>(hs);                                              // #5
    conv_leaky<<<NWORDS / 16, dim3(64, 2), 0, s1>>>(imgB, imgA, conv_w + 2 * CK * CK,
                                                    conv_b + 2, (const int*)0, (const float*)0); // #6 <- ncu
    linear_relu<<<linNW, 256, smem_lin, s1>>>(imgA, W_att_w, W_att_b, hsatt,
                                              (const int*)0, (const float*)0, (float*)0);
    for (int l = 1; l < 3; ++l) {
        linear_relu<<<linNA, 256, smem_lin, s2>>>(xs, W_gnn_w + l * DIM * DIM,
                                                  W_gnn_b + l * DIM, hs,
                                                  (const int*)0, (const float*)0, (float*)0);
        spmm_add<<<NA / 8, 256, 0, s2>>>(hs);
    }
    colsum_partial<<<32, 128, 0, s2>>>(xs, part, NA / 32);
    comb_att<<<1, 128, 0, s2>>>(part, W_att_w, W_att_b);

    // join
    cudaEventRecord(e1, s1);
    cudaEventRecord(e2, s2);
    cudaStreamWaitEvent(0, e1, 0);
    cudaStreamWaitEvent(0, e2, 0);

    // tail (legacy stream)
    protein_partial<<<NWORDS / 64, 128>>>(hsatt);
    final_mlp<<<1, 256>>>(part, W_out_w, W_out_b, W_int_w, W_int_b, out);
}